// round 4
// baseline (speedup 1.0000x reference)
#include <cuda_runtime.h>
#include <cstdint>

#define IN_DIM   1024
#define OUT_DIM  65536
#define BATCH    32
#define NPAIR    16
#define NC       2
#define THREADS  128
#define KSPLIT   4
#define KS       (IN_DIM / KSPLIT)   // 256 k per block
#define GK       4                   // k-rows per pipeline stage
#define NGROUPS  (KS / GK)           // 64
#define NSTAGE   3
#define XS_KT    128                 // x staged in two chunks of 128 k
#define COLS_CTA (THREADS * NC)      // 256 columns per CTA
#define STAGE_BYTES (2 * GK * COLS_CTA * 4)   // 8192 (w + mask)

__device__ float g_partial[KSPLIT * BATCH * OUT_DIM];

__device__ __forceinline__ unsigned long long pack2(float lo, float hi) {
    unsigned long long r;
    asm("mov.b64 %0, {%1, %2};" : "=l"(r) : "f"(lo), "f"(hi));
    return r;
}
__device__ __forceinline__ void unpack2(unsigned long long v, float& lo, float& hi) {
    asm("mov.b64 {%0, %1}, %2;" : "=f"(lo), "=f"(hi) : "l"(v));
}
__device__ __forceinline__ void ffma2(unsigned long long& d,
                                      unsigned long long a,
                                      unsigned long long b) {
    asm("fma.rn.f32x2 %0, %1, %2, %3;" : "=l"(d) : "l"(a), "l"(b), "l"(d));
}
__device__ __forceinline__ uint32_t smem_u32(const void* p) {
    uint32_t a;
    asm("{ .reg .u64 t; cvta.to.shared.u64 t, %1; cvt.u32.u64 %0, t; }"
        : "=r"(a) : "l"(p));
    return a;
}
__device__ __forceinline__ void mbar_init(uint32_t mbar, uint32_t count) {
    asm volatile("mbarrier.init.shared.b64 [%0], %1;" :: "r"(mbar), "r"(count) : "memory");
}
__device__ __forceinline__ void mbar_expect_tx(uint32_t mbar, uint32_t bytes) {
    asm volatile("mbarrier.arrive.expect_tx.shared.b64 _, [%0], %1;"
                 :: "r"(mbar), "r"(bytes) : "memory");
}
__device__ __forceinline__ void mbar_wait(uint32_t mbar, uint32_t parity) {
    asm volatile(
        "{\n\t"
        ".reg .pred P;\n"
        "WAIT_%=:\n\t"
        "mbarrier.try_wait.parity.acquire.cta.shared::cta.b64 P, [%0], %1, 0x989680;\n\t"
        "@!P bra WAIT_%=;\n\t"
        "}"
        :: "r"(mbar), "r"(parity) : "memory");
}
// bulk async copy gmem -> smem, completion via mbarrier tx-bytes
__device__ __forceinline__ void bulk_cp(uint32_t dst, const void* src,
                                        uint32_t bytes, uint32_t mbar) {
    asm volatile(
        "cp.async.bulk.shared::cta.global.mbarrier::complete_tx::bytes [%0], [%1], %2, [%3];"
        :: "r"(dst), "l"(src), "r"(bytes), "r"(mbar) : "memory");
}

__global__ __launch_bounds__(THREADS, 4)
void sparse_linear_main(const float* __restrict__ x,
                        const float* __restrict__ mask,
                        const float* __restrict__ w)
{
    __shared__ alignas(16) unsigned long long xs[XS_KT][NPAIR];        // 16 KB
    __shared__ alignas(16) float wstage[NSTAGE][GK][COLS_CTA];         // 12 KB
    __shared__ alignas(16) float mstage[NSTAGE][GK][COLS_CTA];         // 12 KB
    __shared__ alignas(8)  unsigned long long mbar_mem[NSTAGE];

    const int split   = blockIdx.y;
    const int kbase   = split * KS;
    const int colbase = blockIdx.x * COLS_CTA;
    const int tid     = threadIdx.x;

    const uint32_t mbar0 = smem_u32(&mbar_mem[0]);
    const uint32_t wst0  = smem_u32(&wstage[0][0][0]);
    const uint32_t mst0  = smem_u32(&mstage[0][0][0]);

    if (tid == 0) {
#pragma unroll
        for (int s = 0; s < NSTAGE; s++) mbar_init(mbar0 + 8 * s, 1);
    }
    __syncthreads();

    // Issue the first NSTAGE stages immediately (DRAM starts now).
    const float* wsrc = w    + (size_t)kbase * OUT_DIM + colbase;
    const float* msrc = mask + (size_t)kbase * OUT_DIM + colbase;
    if (tid == 0) {
#pragma unroll
        for (int s = 0; s < NSTAGE; s++) {
            mbar_expect_tx(mbar0 + 8 * s, STAGE_BYTES);
#pragma unroll
            for (int u = 0; u < GK; u++) {
                const size_t off = (size_t)(s * GK + u) * OUT_DIM;
                bulk_cp(wst0 + (s * GK + u) * COLS_CTA * 4, wsrc + off,
                        COLS_CTA * 4, mbar0 + 8 * s);
                bulk_cp(mst0 + (s * GK + u) * COLS_CTA * 4, msrc + off,
                        COLS_CTA * 4, mbar0 + 8 * s);
            }
        }
    }

    // Stage x chunk 0 while the bulk copies fly.
    for (int idx = tid; idx < XS_KT * NPAIR; idx += THREADS) {
        int k = idx / NPAIR, p = idx % NPAIR;
        xs[k][p] = pack2(x[(size_t)(2 * p)     * IN_DIM + kbase + k],
                         x[(size_t)(2 * p + 1) * IN_DIM + kbase + k]);
    }
    __syncthreads();

    unsigned long long acc[NPAIR][NC];
#pragma unroll
    for (int p = 0; p < NPAIR; p++)
#pragma unroll
        for (int c = 0; c < NC; c++) acc[p][c] = 0ULL;

    int s = 0, phase = 0;
#pragma unroll 1
    for (int g = 0; g < NGROUPS; ++g) {
        if (g == XS_KT / GK) {   // restage x chunk 1 (prev groups all synced)
            for (int idx = tid; idx < XS_KT * NPAIR; idx += THREADS) {
                int k = idx / NPAIR, p = idx % NPAIR;
                xs[k][p] = pack2(x[(size_t)(2 * p)     * IN_DIM + kbase + XS_KT + k],
                                 x[(size_t)(2 * p + 1) * IN_DIM + kbase + XS_KT + k]);
            }
            __syncthreads();
        }

        mbar_wait(mbar0 + 8 * s, phase);

#pragma unroll
        for (int u = 0; u < GK; u++) {
            const float2 wv = *reinterpret_cast<const float2*>(&wstage[s][u][NC * tid]);
            const float2 mv = *reinterpret_cast<const float2*>(&mstage[s][u][NC * tid]);
            const float m0 = wv.x * mv.x;
            const float m1 = wv.y * mv.y;
            const unsigned long long bb0 = pack2(m0, m0);
            const unsigned long long bb1 = pack2(m1, m1);
            const ulonglong2* xr =
                reinterpret_cast<const ulonglong2*>(&xs[(g * GK + u) & (XS_KT - 1)][0]);
#pragma unroll
            for (int q = 0; q < NPAIR / 2; q++) {
                const ulonglong2 xv = xr[q];
                ffma2(acc[2 * q][0],     xv.x, bb0);
                ffma2(acc[2 * q][1],     xv.x, bb1);
                ffma2(acc[2 * q + 1][0], xv.y, bb0);
                ffma2(acc[2 * q + 1][1], xv.y, bb1);
            }
        }

        __syncthreads();   // all warps done reading stage s

        if (g + NSTAGE < NGROUPS && tid == 0) {
            mbar_expect_tx(mbar0 + 8 * s, STAGE_BYTES);
#pragma unroll
            for (int u = 0; u < GK; u++) {
                const size_t off = (size_t)((g + NSTAGE) * GK + u) * OUT_DIM;
                bulk_cp(wst0 + (s * GK + u) * COLS_CTA * 4, wsrc + off,
                        COLS_CTA * 4, mbar0 + 8 * s);
                bulk_cp(mst0 + (s * GK + u) * COLS_CTA * 4, msrc + off,
                        COLS_CTA * 4, mbar0 + 8 * s);
            }
        }
        if (++s == NSTAGE) { s = 0; phase ^= 1; }
    }

    const int col0 = colbase + NC * tid;
    float* part = g_partial + (size_t)split * BATCH * OUT_DIM;
#pragma unroll
    for (int p = 0; p < NPAIR; p++) {
        float a0lo, a0hi, a1lo, a1hi;
        unpack2(acc[p][0], a0lo, a0hi);
        unpack2(acc[p][1], a1lo, a1hi);
        *reinterpret_cast<float2*>(part + (size_t)(2 * p)     * OUT_DIM + col0) =
            make_float2(a0lo, a1lo);
        *reinterpret_cast<float2*>(part + (size_t)(2 * p + 1) * OUT_DIM + col0) =
            make_float2(a0hi, a1hi);
    }
}

__global__ __launch_bounds__(256)
void sparse_linear_reduce(const float* __restrict__ bias, float* __restrict__ out)
{
    const size_t i = (size_t)blockIdx.x * blockDim.x + threadIdx.x;
    const size_t elem = i * 8;                       // two float4s per thread
    const int col = (int)(elem % OUT_DIM);

    float4 v[KSPLIT][2];
#pragma unroll
    for (int sp = 0; sp < KSPLIT; sp++) {
        const float* src = g_partial + (size_t)sp * BATCH * OUT_DIM + elem;
        v[sp][0] = *reinterpret_cast<const float4*>(src);
        v[sp][1] = *reinterpret_cast<const float4*>(src + 4);
    }
    float4 b0 = *reinterpret_cast<const float4*>(bias + col);
    float4 b1 = *reinterpret_cast<const float4*>(bias + col + 4);
#pragma unroll
    for (int sp = 1; sp < KSPLIT; sp++) {
        v[0][0].x += v[sp][0].x; v[0][0].y += v[sp][0].y;
        v[0][0].z += v[sp][0].z; v[0][0].w += v[sp][0].w;
        v[0][1].x += v[sp][1].x; v[0][1].y += v[sp][1].y;
        v[0][1].z += v[sp][1].z; v[0][1].w += v[sp][1].w;
    }
    v[0][0].x += b0.x; v[0][0].y += b0.y; v[0][0].z += b0.z; v[0][0].w += b0.w;
    v[0][1].x += b1.x; v[0][1].y += b1.y; v[0][1].z += b1.z; v[0][1].w += b1.w;
    *reinterpret_cast<float4*>(out + elem)     = v[0][0];
    *reinterpret_cast<float4*>(out + elem + 4) = v[0][1];
}

extern "C" void kernel_launch(void* const* d_in, const int* in_sizes, int n_in,
                              void* d_out, int out_size) {
    const float* x    = (const float*)d_in[0];
    const float* mask = (const float*)d_in[1];
    const float* w    = (const float*)d_in[2];
    const float* bias = (const float*)d_in[3];
    float* out = (float*)d_out;

    dim3 grid(OUT_DIM / COLS_CTA, KSPLIT);       // (256, 4)
    sparse_linear_main<<<grid, THREADS>>>(x, mask, w);

    const int total8 = BATCH * OUT_DIM / 8;      // 262144
    sparse_linear_reduce<<<total8 / 256, 256>>>(bias, out);
}